// round 4
// baseline (speedup 1.0000x reference)
#include <cuda_runtime.h>
#include <cuda_bf16.h>
#include <math.h>

// DecodeSBP: per-keypoint argmax over sigmoid heatmaps.
// x: [1, 133, 512, 512] fp32.  out: [133,3] = (x*4, y*4, conf) or (-4,-4,-1).
// sigmoid monotonic -> argmax(sigmoid) == argmax; sigmoid only on the max.
//
// 148 CTAs x 1024 threads, single wave, flat equal segments. Inner loop has a
// COMPILE-TIME-CONSTANT trip count (57) so ptxas front-batches the LDG.128s
// (this was lost in rounds 2/3 with runtime loop bounds -> DRAM% collapsed).
// Segment spans <=2 keypoints; a per-element predicate routes into one of two
// accumulator pairs. Block-reduce 64-bit keys (monotonic bits<<32 | ~idx) and
// atomicMax into g_best[k]: max key == max value, smallest index on ties.

#define KPTS   133
#define HW     (512 * 512)
#define HW4    65536                 // float4 per keypoint
#define W      512
#define SCALE  4.0f
#define CONF_THRESHOLD 0.8f

#define NT      1024
#define GRID    148
#define N4      (KPTS * HW4)         // 8,716,288
#define SEG     58894                // ceil(N4/148); last CTA gets 58,870
#define MAIN_IT 57                   // 57*1024 = 58,368 <= 58,870 (all CTAs)

__device__ unsigned long long g_best[KPTS];   // zero == -inf key
__device__ unsigned int g_count = 0;

__device__ __forceinline__ unsigned int float_to_key(float f) {
    unsigned int u = __float_as_uint(f);
    return u ^ ((unsigned int)((int)u >> 31) | 0x80000000u);
}
__device__ __forceinline__ float key_to_float(unsigned int k) {
    unsigned int u = (k & 0x80000000u) ? (k ^ 0x80000000u) : ~k;
    return __uint_as_float(u);
}

// Block-reduce (best, global_idx) and atomicMax into g_best[k] (local idx).
__device__ __forceinline__ void flush_kpt(float best, int gidx, int k,
                                          unsigned long long* s_key) {
    const int local = gidx - (k << 18);          // k * HW
    unsigned long long key =
        ((unsigned long long)float_to_key(best) << 32) | (unsigned int)(~local);
    #pragma unroll
    for (int off = 16; off > 0; off >>= 1) {
        unsigned long long o = __shfl_down_sync(0xFFFFFFFFu, key, off);
        if (o > key) key = o;
    }
    const int tid = threadIdx.x, lane = tid & 31, wid = tid >> 5;
    if (lane == 0) s_key[wid] = key;
    __syncthreads();
    if (tid == 0) {
        #pragma unroll
        for (int w = 1; w < NT / 32; w++)
            if (s_key[w] > key) key = s_key[w];
        atomicMax(&g_best[k], key);
    }
    __syncthreads();
}

__global__ __launch_bounds__(NT, 1)
void decode_sbp_kernel(const float* __restrict__ x, float* __restrict__ out) {
    const float4* __restrict__ p4 = reinterpret_cast<const float4*>(x);
    __shared__ unsigned long long s_key[NT / 32];
    __shared__ int s_last;

    const int tid = threadIdx.x;
    const int s   = blockIdx.x * SEG;
    const int e   = min(s + SEG, N4);
    const int k0  = s >> 16;                     // / HW4
    const int k1  = (e - 1) >> 16;
    const int bnd = (k1 == k0) ? e : (k1 << 16); // boundary (multiple of 1024)

    float bestA = -INFINITY; int idxA = 0;       // keypoint k0 side
    float bestB = -INFINITY; int idxB = 0;       // keypoint k1 side

    // Constant trip count, literal stride -> batched LDG.128.
    // Per-thread global indices strictly increase -> '>' keeps first occurrence.
    int j = s + tid;
    #pragma unroll 8
    for (int it = 0; it < MAIN_IT; it++, j += NT) {
        float4 v = p4[j];
        const int b = j << 2;
        if (j < bnd) {
            if (v.x > bestA) { bestA = v.x; idxA = b;     }
            if (v.y > bestA) { bestA = v.y; idxA = b + 1; }
            if (v.z > bestA) { bestA = v.z; idxA = b + 2; }
            if (v.w > bestA) { bestA = v.w; idxA = b + 3; }
        } else {
            if (v.x > bestB) { bestB = v.x; idxB = b;     }
            if (v.y > bestB) { bestB = v.y; idxB = b + 1; }
            if (v.z > bestB) { bestB = v.z; idxB = b + 2; }
            if (v.w > bestB) { bestB = v.w; idxB = b + 3; }
        }
    }
    // Tail: at most one more float4 per thread.
    if (j < e) {
        float4 v = p4[j];
        const int b = j << 2;
        if (j < bnd) {
            if (v.x > bestA) { bestA = v.x; idxA = b;     }
            if (v.y > bestA) { bestA = v.y; idxA = b + 1; }
            if (v.z > bestA) { bestA = v.z; idxA = b + 2; }
            if (v.w > bestA) { bestA = v.w; idxA = b + 3; }
        } else {
            if (v.x > bestB) { bestB = v.x; idxB = b;     }
            if (v.y > bestB) { bestB = v.y; idxB = b + 1; }
            if (v.z > bestB) { bestB = v.z; idxB = b + 2; }
            if (v.w > bestB) { bestB = v.w; idxB = b + 3; }
        }
    }

    flush_kpt(bestA, idxA, k0, s_key);
    if (k1 != k0) flush_kpt(bestB, idxB, k1, s_key);
    // Threads that never touched a side hold (-inf, 0): the -inf key loses to
    // any finite value's key, so it can never win a keypoint (data is finite).

    if (tid == 0) {
        __threadfence();
        unsigned int old = atomicAdd(&g_count, 1u);
        s_last = (old == GRID - 1) ? 1 : 0;
    }
    __syncthreads();

    if (s_last) {
        __threadfence();
        if (tid < KPTS) {
            const unsigned long long m = g_best[tid];
            const float mv  = key_to_float((unsigned int)(m >> 32));
            const int   idx = (int)~(unsigned int)(m & 0xFFFFFFFFu);
            const float conf = 1.0f / (1.0f + __expf(-mv));
            const bool valid = conf > CONF_THRESHOLD;
            const float yy = (float)(idx / W);
            const float xx = (float)(idx % W);
            out[tid * 3 + 0] = valid ? xx * SCALE : -SCALE;
            out[tid * 3 + 1] = valid ? yy * SCALE : -SCALE;
            out[tid * 3 + 2] = valid ? conf : -1.0f;
            g_best[tid] = 0ull;        // reset for next graph replay
        }
        if (tid == 0) g_count = 0;
    }
}

extern "C" void kernel_launch(void* const* d_in, const int* in_sizes, int n_in,
                              void* d_out, int out_size) {
    const float* x = (const float*)d_in[0];
    float* out = (float*)d_out;
    decode_sbp_kernel<<<GRID, NT>>>(x, out);
}

// round 5
// speedup vs baseline: 1.5822x; 1.5822x over previous
#include <cuda_runtime.h>
#include <cuda_bf16.h>
#include <math.h>

// DecodeSBP: per-keypoint argmax over sigmoid heatmaps.
// x: [1, 133, 512, 512] fp32.  out: [133,3] = (x*4, y*4, conf) or (-4,-4,-1).
// sigmoid monotonic -> argmax(sigmoid) == argmax; sigmoid only on the max.
//
// Codegen contract (learned rounds 1-4): the inner loop MUST have a literal
// trip count, a branch-free body, and no register cap, so ptxas front-batches
// the unrolled LDG.128s (MLP_p1=8). Any deviation collapsed DRAM% (74->43).
//
// Grid (8 chunks x 133 kpts) x 256 threads: chunks align to keypoints (no
// boundary logic), ~5 CTAs/SM resident -> all 148 SMs busy (R1 left 15 idle).
// Merge: block-reduce a 64-bit key (monotonic float bits << 32 | ~idx) and
// atomicMax into g_best[k] -> max value, smallest index on ties (first
// occurrence, matching jnp.argmax). Last finishing CTA decodes + resets.

#define KPTS   133
#define HW     (512 * 512)
#define HW4    65536                 // float4 per keypoint
#define W      512
#define SCALE  4.0f
#define CONF_THRESHOLD 0.8f

#define CHUNKS 8
#define NT     256
#define CHUNK_VEC (HW4 / CHUNKS)     // 8192 float4 per chunk
#define ITERS  (CHUNK_VEC / NT)      // 32
#define NBLOCKS (KPTS * CHUNKS)      // 1064

__device__ unsigned long long g_best[KPTS];   // zero-init: loses to any finite value
__device__ unsigned int g_count = 0;

__device__ __forceinline__ unsigned int float_to_key(float f) {
    unsigned int u = __float_as_uint(f);
    return u ^ ((unsigned int)((int)u >> 31) | 0x80000000u);
}
__device__ __forceinline__ float key_to_float(unsigned int k) {
    unsigned int u = (k & 0x80000000u) ? (k ^ 0x80000000u) : ~k;
    return __uint_as_float(u);
}

__global__ __launch_bounds__(NT)
void decode_sbp_kernel(const float* __restrict__ x, float* __restrict__ out) {
    const int c = blockIdx.x;
    const int k = blockIdx.y;
    const float4* __restrict__ p4 =
        reinterpret_cast<const float4*>(x + (size_t)k * HW);

    const int tid = threadIdx.x;

    float best = -INFINITY;
    int bidx = 0;

    // Literal trip count (32), literal stride, branch-free body.
    // Per-thread indices strictly increase -> strict '>' keeps first occurrence.
    int j = c * CHUNK_VEC + tid;
    #pragma unroll 8
    for (int it = 0; it < ITERS; it++, j += NT) {
        float4 v = p4[j];
        const int b = j << 2;        // local index within keypoint
        if (v.x > best) { best = v.x; bidx = b;     }
        if (v.y > best) { best = v.y; bidx = b + 1; }
        if (v.z > best) { best = v.z; bidx = b + 2; }
        if (v.w > best) { best = v.w; bidx = b + 3; }
    }

    // 64-bit max-reducible key: value-monotonic bits, ~idx for min-index ties.
    unsigned long long key =
        ((unsigned long long)float_to_key(best) << 32) | (unsigned int)(~bidx);

    #pragma unroll
    for (int off = 16; off > 0; off >>= 1) {
        unsigned long long o = __shfl_down_sync(0xFFFFFFFFu, key, off);
        if (o > key) key = o;
    }

    __shared__ unsigned long long s_key[NT / 32];
    __shared__ int s_last;
    const int lane = tid & 31;
    const int wid  = tid >> 5;
    if (lane == 0) s_key[wid] = key;
    __syncthreads();

    if (tid == 0) {
        #pragma unroll
        for (int w = 1; w < NT / 32; w++)
            if (s_key[w] > key) key = s_key[w];
        atomicMax(&g_best[k], key);
        __threadfence();
        unsigned int old = atomicAdd(&g_count, 1u);
        s_last = (old == NBLOCKS - 1) ? 1 : 0;
    }
    __syncthreads();

    if (s_last) {
        __threadfence();
        if (tid < KPTS) {
            const unsigned long long m = g_best[tid];
            const float mv  = key_to_float((unsigned int)(m >> 32));
            const int   idx = (int)~(unsigned int)(m & 0xFFFFFFFFu);
            const float conf = 1.0f / (1.0f + __expf(-mv));
            const bool valid = conf > CONF_THRESHOLD;
            const float yy = (float)(idx / W);
            const float xx = (float)(idx % W);
            out[tid * 3 + 0] = valid ? xx * SCALE : -SCALE;
            out[tid * 3 + 1] = valid ? yy * SCALE : -SCALE;
            out[tid * 3 + 2] = valid ? conf : -1.0f;
            g_best[tid] = 0ull;      // reset for next graph replay
        }
        if (tid == 0) g_count = 0;
    }
}

extern "C" void kernel_launch(void* const* d_in, const int* in_sizes, int n_in,
                              void* d_out, int out_size) {
    const float* x = (const float*)d_in[0];
    float* out = (float*)d_out;
    dim3 grid(CHUNKS, KPTS);
    decode_sbp_kernel<<<grid, NT>>>(x, out);
}

// round 6
// speedup vs baseline: 1.6120x; 1.0189x over previous
#include <cuda_runtime.h>
#include <cuda_bf16.h>
#include <math.h>

// DecodeSBP: per-keypoint argmax over sigmoid heatmaps.
// x: [1, 133, 512, 512] fp32.  out: [133,3] = (x*4, y*4, conf) or (-4,-4,-1).
// sigmoid monotonic -> argmax(sigmoid) == argmax; sigmoid only on the max.
//
// Codegen contract (rounds 1-5): DRAM% tracks the number of LDG.128s in
// flight. ptxas would not front-batch on its own (kept choosing 32 regs),
// so this version loads 8 float4 into an explicit register array BEFORE any
// compare -> 8 back-to-back LDG.128 per group, 4 groups per CTA.
// __launch_bounds__(256, 4) gives a 64-reg budget (no 32-reg throttle) and
// 4 CTAs/SM = 32 warps/SM, which R1 proved sufficient for a memory-bound loop.
//
// Grid (8 chunks x 133 kpts) x 256 threads, chunks aligned to keypoints.
// Merge: block-reduce 64-bit key (monotonic float bits << 32 | ~idx),
// atomicMax into g_best[k] -> max value, smallest index on ties. Last
// finishing CTA decodes and resets state for graph replay.

#define KPTS   133
#define HW     (512 * 512)
#define HW4    65536
#define W      512
#define SCALE  4.0f
#define CONF_THRESHOLD 0.8f

#define CHUNKS 8
#define NT     256
#define CHUNK_VEC (HW4 / CHUNKS)     // 8192 float4 per chunk
#define UB     8                     // loads batched per group
#define GROUPS (CHUNK_VEC / (NT * UB))  // 4
#define NBLOCKS (KPTS * CHUNKS)      // 1064

__device__ unsigned long long g_best[KPTS];   // zero-init: loses to any finite value
__device__ unsigned int g_count = 0;

__device__ __forceinline__ unsigned int float_to_key(float f) {
    unsigned int u = __float_as_uint(f);
    return u ^ ((unsigned int)((int)u >> 31) | 0x80000000u);
}
__device__ __forceinline__ float key_to_float(unsigned int k) {
    unsigned int u = (k & 0x80000000u) ? (k ^ 0x80000000u) : ~k;
    return __uint_as_float(u);
}

__global__ __launch_bounds__(NT, 4)
void decode_sbp_kernel(const float* __restrict__ x, float* __restrict__ out) {
    const int c = blockIdx.x;
    const int k = blockIdx.y;
    const float4* __restrict__ p4 =
        reinterpret_cast<const float4*>(x + (size_t)k * HW);

    const int tid = threadIdx.x;

    float best = -INFINITY;
    int bidx = 0;

    // 4 groups x (8 batched LDG.128 -> then compare). All loads of a group
    // are issued before any use. Indices increase within and across groups,
    // so strict '>' preserves first-occurrence argmax.
    int j = c * CHUNK_VEC + tid;
    #pragma unroll
    for (int g = 0; g < GROUPS; g++) {
        float4 v[UB];
        #pragma unroll
        for (int u = 0; u < UB; u++)
            v[u] = p4[j + u * NT];
        #pragma unroll
        for (int u = 0; u < UB; u++) {
            const int b = (j + u * NT) << 2;   // local index within keypoint
            if (v[u].x > best) { best = v[u].x; bidx = b;     }
            if (v[u].y > best) { best = v[u].y; bidx = b + 1; }
            if (v[u].z > best) { best = v[u].z; bidx = b + 2; }
            if (v[u].w > best) { best = v[u].w; bidx = b + 3; }
        }
        j += UB * NT;
    }

    // 64-bit max-reducible key: value-monotonic bits, ~idx for min-index ties.
    unsigned long long key =
        ((unsigned long long)float_to_key(best) << 32) | (unsigned int)(~bidx);

    #pragma unroll
    for (int off = 16; off > 0; off >>= 1) {
        unsigned long long o = __shfl_down_sync(0xFFFFFFFFu, key, off);
        if (o > key) key = o;
    }

    __shared__ unsigned long long s_key[NT / 32];
    __shared__ int s_last;
    const int lane = tid & 31;
    const int wid  = tid >> 5;
    if (lane == 0) s_key[wid] = key;
    __syncthreads();

    if (tid == 0) {
        #pragma unroll
        for (int w = 1; w < NT / 32; w++)
            if (s_key[w] > key) key = s_key[w];
        atomicMax(&g_best[k], key);
        __threadfence();
        unsigned int old = atomicAdd(&g_count, 1u);
        s_last = (old == NBLOCKS - 1) ? 1 : 0;
    }
    __syncthreads();

    if (s_last) {
        __threadfence();
        if (tid < KPTS) {
            const unsigned long long m = g_best[tid];
            const float mv  = key_to_float((unsigned int)(m >> 32));
            const int   idx = (int)~(unsigned int)(m & 0xFFFFFFFFu);
            const float conf = 1.0f / (1.0f + __expf(-mv));
            const bool valid = conf > CONF_THRESHOLD;
            const float yy = (float)(idx / W);
            const float xx = (float)(idx % W);
            out[tid * 3 + 0] = valid ? xx * SCALE : -SCALE;
            out[tid * 3 + 1] = valid ? yy * SCALE : -SCALE;
            out[tid * 3 + 2] = valid ? conf : -1.0f;
            g_best[tid] = 0ull;      // reset for next graph replay
        }
        if (tid == 0) g_count = 0;
    }
}

extern "C" void kernel_launch(void* const* d_in, const int* in_sizes, int n_in,
                              void* d_out, int out_size) {
    const float* x = (const float*)d_in[0];
    float* out = (float*)d_out;
    dim3 grid(CHUNKS, KPTS);
    decode_sbp_kernel<<<grid, NT>>>(x, out);
}